// round 7
// baseline (speedup 1.0000x reference)
#include <cuda_runtime.h>
#include <cuda_bf16.h>
#include <cuda_pipeline_primitives.h>

// GraphAttentionLayer: out = elu(softmax(h_j @ a_j + const) @ h_j)
// SINGLE kernel. cp.async (LDGSTS) ring: each warp keeps DEPTH=6 rows
// (3KB) in flight global->smem with no register buffers, decoupling load
// issue from the shuffle/exp consumption chain. Rare-rescale online softmax.
// Last-block-done finalize combines partials L2-hot.
// h_i . a_i is a constant logit shift -> cancels in softmax -> skipped.

#define D        128
#define NB       296          // blocks (2 * 148 SMs -> balanced 2-wave)
#define NT       512          // threads per block
#define WPB      (NT / 32)    // 16 warps
#define NW       (NB * WPB)
#define GRP      (NT / D)     // 4 finalize groups over the dim axis
#define DEPTH    6            // per-warp ring slots (rows in flight)
#define ROWB     512          // bytes per row (128 f32)

__device__ float g_m[NB];
__device__ float g_s[NB];
__device__ float g_acc[NB * D];
__device__ unsigned int g_count;

__device__ __forceinline__ float dot4(const float4& h, const float4& a) {
    return h.x * a.x + h.y * a.y + h.z * a.z + h.w * a.w;
}

// d is warp-uniform. Rescale only when a new max appears (rare).
__device__ __forceinline__ void upd(float d, const float4& h,
                                    float& m, float& s, float4& acc) {
    if (d > m) {
        float c = __expf(m - d);
        s = s * c + 1.0f;
        acc.x = acc.x * c + h.x;
        acc.y = acc.y * c + h.y;
        acc.z = acc.z * c + h.z;
        acc.w = acc.w * c + h.w;
        m = d;
    } else {
        float w = __expf(d - m);
        s += w;
        acc.x += w * h.x;
        acc.y += w * h.y;
        acc.z += w * h.z;
        acc.w += w * h.w;
    }
}

__global__ __launch_bounds__(NT, 2)
void gat_fused(const float* __restrict__ hj, const float* __restrict__ a,
               int nrows, float* __restrict__ out) {
    const int warp = threadIdx.x >> 5;
    const int lane = threadIdx.x & 31;

    // 48KB static smem: cp.async tile ring during the main loop,
    // aliased as combine scratch afterwards (tile is dead by then).
    __shared__ __align__(16) unsigned char sraw[WPB * DEPTH * ROWB];
    unsigned char* ring = sraw + warp * (DEPTH * ROWB) + lane * 16;

    const float4 aj = *reinterpret_cast<const float4*>(a + D + lane * 4);

    const int gw    = blockIdx.x * WPB + warp;
    const int chunk = (nrows + NW - 1) / NW;
    int r0 = gw * chunk;
    int r1 = r0 + chunk;
    if (r0 > nrows) r0 = nrows;
    if (r1 > nrows) r1 = nrows;
    const int n = (r1 > r0) ? (r1 - r0) : 0;

    const float* base = hj + (size_t)r0 * D + lane * 4;

    // Prologue: fill the ring (always commit DEPTH groups, empty ones ok)
    #pragma unroll
    for (int k = 0; k < DEPTH; ++k) {
        if (k < n)
            __pipeline_memcpy_async(ring + k * ROWB, base + (size_t)k * D, 16);
        __pipeline_commit();
    }

    float  m = -1e30f;
    float  s = 0.0f;
    float4 acc = make_float4(0.f, 0.f, 0.f, 0.f);

    int slot = 0;
    for (int r = 0; r < n; ++r) {
        __pipeline_wait_prior(DEPTH - 1);          // row r's group retired
        float4 h = *reinterpret_cast<const float4*>(ring + slot * ROWB);

        // refill this slot with row r+DEPTH (write lands ~600cyc later,
        // long after the LDS above has read)
        int k = r + DEPTH;
        if (k < n)
            __pipeline_memcpy_async(ring + slot * ROWB, base + (size_t)k * D, 16);
        __pipeline_commit();

        float d = dot4(h, aj);
        #pragma unroll
        for (int o = 16; o > 0; o >>= 1)
            d += __shfl_xor_sync(0xffffffffu, d, o);

        upd(d, h, m, s, acc);

        if (++slot == DEPTH) slot = 0;
    }
    __pipeline_wait_prior(0);                      // drain (empties only)

    // ---- Block combine (aliased into sraw; tile contents dead) ----
    __syncthreads();
    float* sm_acc = reinterpret_cast<float*>(sraw);                 // [WPB][D] 8KB
    float* sm_m   = reinterpret_cast<float*>(sraw + 8192);          // [WPB]
    float* sm_s   = reinterpret_cast<float*>(sraw + 8192 + 64);     // [WPB]
    float* red    = reinterpret_cast<float*>(sraw + 8192 + 128);    // [WPB]
    float* sm_MS  = reinterpret_cast<float*>(sraw + 8192 + 192);    // M, S
    float* sm_c   = reinterpret_cast<float*>(sraw + 8192 + 256);    // [NB]
    float* sm_part= reinterpret_cast<float*>(sraw + 8192 + 256 + NB * 4 + 16); // [GRP][D]

    if (lane == 0) { sm_m[warp] = m; sm_s[warp] = s; }
    *reinterpret_cast<float4*>(&sm_acc[warp * D + lane * 4]) = acc;
    __syncthreads();

    if (threadIdx.x < D) {
        const int d = threadIdx.x;
        float M = -1e30f;
        #pragma unroll
        for (int w = 0; w < WPB; ++w) M = fmaxf(M, sm_m[w]);

        float st = 0.f, ad = 0.f;
        #pragma unroll
        for (int w = 0; w < WPB; ++w) {
            float c = __expf(sm_m[w] - M);
            st += sm_s[w] * c;
            ad += sm_acc[w * D + d] * c;
        }
        g_acc[blockIdx.x * D + d] = ad;
        if (d == 0) { g_m[blockIdx.x] = M; g_s[blockIdx.x] = st; }
    }

    // ---- Last-block-done finalize (partials L2-hot) ----
    __threadfence();
    __shared__ bool isLast;
    if (threadIdx.x == 0) {
        unsigned v = atomicAdd(&g_count, 1u);
        isLast = (v == NB - 1);
    }
    __syncthreads();
    if (!isLast) return;
    if (threadIdx.x == 0) g_count = 0;             // reset for graph replay

    const int t = threadIdx.x;

    float mreg = (t < NB) ? __ldcg(&g_m[t]) : -1e30f;
    float mv = mreg;
    #pragma unroll
    for (int o = 16; o > 0; o >>= 1) mv = fmaxf(mv, __shfl_xor_sync(0xffffffffu, mv, o));
    if (lane == 0) red[warp] = mv;
    __syncthreads();
    if (t == 0) {
        float v = red[0];
        #pragma unroll
        for (int w = 1; w < WPB; ++w) v = fmaxf(v, red[w]);
        sm_MS[0] = v;
    }
    __syncthreads();
    const float M = sm_MS[0];

    float sv = 0.f;
    if (t < NB) {
        float c = __expf(mreg - M);
        sm_c[t] = c;
        sv = __ldcg(&g_s[t]) * c;
    }
    #pragma unroll
    for (int o = 16; o > 0; o >>= 1) sv += __shfl_xor_sync(0xffffffffu, sv, o);
    __syncthreads();
    if (lane == 0) red[warp] = sv;
    __syncthreads();
    if (t == 0) {
        float v = 0.f;
        #pragma unroll
        for (int w = 0; w < WPB; ++w) v += red[w];
        sm_MS[1] = v;
    }
    __syncthreads();

    const int d   = t & (D - 1);
    const int grp = t >> 7;
    float ad = 0.f;
    for (int b = grp; b < NB; b += GRP)
        ad += __ldcg(&g_acc[b * D + d]) * sm_c[b];
    sm_part[grp * D + d] = ad;
    __syncthreads();

    if (t < D) {
        float total = 0.f;
        #pragma unroll
        for (int g = 0; g < GRP; ++g) total += sm_part[g * D + t];
        float h = total / sm_MS[1];
        out[t] = (h > 0.f) ? h : expm1f(h);        // ELU, alpha = 1
    }
}

extern "C" void kernel_launch(void* const* d_in, const int* in_sizes, int n_in,
                              void* d_out, int out_size) {
    // inputs: [0] h_i (unused: constant logit shift cancels in softmax),
    //         [1] h_j [200000,128] f32, [2] a [256,1] f32
    const float* hj = (const float*)d_in[1];
    const float* a  = (const float*)d_in[2];
    const int nrows = in_sizes[1] / D;

    gat_fused<<<NB, NT>>>(hj, a, nrows, (float*)d_out);
}